// round 11
// baseline (speedup 1.0000x reference)
#include <cuda_runtime.h>
#include <math.h>
#include <stdint.h>

#define BN   4
#define VN   256
#define C1N  64
#define C2N  32
#define H0N  128
#define H2N  256

// ---------------- scratch ----------------
__device__ float g_A [BN*VN*H0N];
__device__ float g_Bv[BN*VN*H0N];
__device__ float g_x1[BN*VN*H0N];
__device__ float g_x2[BN*VN*H0N];
__device__ float g_P [BN*VN*H2N];
__device__ float g_Q [BN*VN*H2N];

__device__ __forceinline__ uint32_t f32_to_tf32(float x) {
    uint32_t r;
    asm("cvt.rna.tf32.f32 %0, %1;" : "=r"(r) : "f"(x));
    return r;
}
__device__ __forceinline__ void mma_16x8x8(float* c, const uint32_t* a, const uint32_t* b) {
    asm volatile("mma.sync.aligned.m16n8k8.row.col.f32.tf32.tf32.f32 "
        "{%0,%1,%2,%3}, {%4,%5,%6,%7}, {%8,%9}, {%0,%1,%2,%3};"
        : "+f"(c[0]), "+f"(c[1]), "+f"(c[2]), "+f"(c[3])
        : "r"(a[0]), "r"(a[1]), "r"(a[2]), "r"(a[3]), "r"(b[0]), "r"(b[1]));
}

// SMEM layout in 4-byte words.
// W1E: [32 k][n] stride 132 (k-major). W2: [128 k][n] stride 132.
// E:   2 buffers of [64 j][k] stride 36.  BN: 2 buffers of [64 j][n] stride 132.
// H1:  [64 j][k] stride 132.
#define OFF_W1E 0
#define OFF_W2  (OFF_W1E + 32*132)        //  4224
#define OFF_E   (OFF_W2  + 128*132)       // 21120
#define OFF_BN  (OFF_E   + 2*64*36)       // 25728
#define OFF_H1  (OFF_BN  + 2*64*132)      // 42624
#define OFF_A   (OFF_H1  + 64*132)        // 51072
#define OFF_B2  (OFF_A + 128)
#define OFF_ADJ (OFF_B2 + 128)
#define OFF_RED (OFF_ADJ + 256)
#define SMEM_WORDS (OFF_RED + 2*132)
#define SMEM_BYTES (SMEM_WORDS * 4)       // ~207.5 KB

// ---------------------------------------------------------------------------
// prep_node: 256 CTAs x 4 nodes, 128 threads.
template<int C>
__global__ void prep_node3(const float* __restrict__ x,
                           const float* __restrict__ W1,
                           const float* __restrict__ b1,
                           float* __restrict__ A,
                           float* __restrict__ Bout)
{
    __shared__ float sx[4 * C];
    const int ni0 = blockIdx.x * 4;
    const int h   = threadIdx.x;     // 128
    for (int idx = h; idx < 4 * C; idx += 128)
        sx[idx] = x[(size_t)ni0 * C + idx];
    __syncthreads();
    float accA[4] = {0.f, 0.f, 0.f, 0.f};
    float accB[4] = {0.f, 0.f, 0.f, 0.f};
#pragma unroll 4
    for (int c = 0; c < C; c++) {
        float wa = W1[c * 128 + h];
        float wb = W1[(C + c) * 128 + h];
        float d  = wa - wb;
#pragma unroll
        for (int r = 0; r < 4; r++) {
            float xa = sx[r * C + c];
            accA[r] += xa * d;
            accB[r] += xa * wb;
        }
    }
    const float bb = b1[h];
#pragma unroll
    for (int r = 0; r < 4; r++) {
        A   [(size_t)(ni0 + r) * 128 + h] = accA[r] + bb;
        Bout[(size_t)(ni0 + r) * 128 + h] = accB[r];
    }
}

// ---------------------------------------------------------------------------
// Fused edgeconv, pipelined: 4 chunks of 64 j-rows; E+Bnode double-buffered,
// prefetched one chunk ahead so no gmem sits on the barrier-serialized path.
// One CTA per (b,i), 256 threads = 8 warps (2 M-groups x 4 N-groups).
__global__ __launch_bounds__(256, 1)
void fused_ec_pipe(const int*   __restrict__ adj,
                   const float* __restrict__ e,       // (B,V,V,32)
                   const float* __restrict__ A,
                   const float* __restrict__ Bnode,
                   const float* __restrict__ W1e,     // (32,128)
                   const float* __restrict__ W2,      // (128,128)
                   const float* __restrict__ b2,
                   float* __restrict__ xout)
{
    extern __shared__ float smem[];
    uint32_t* s32 = (uint32_t*)smem;
    const int tid  = threadIdx.x;
    const int lane = tid & 31;
    const int wid  = tid >> 5;
    const int gid  = lane >> 2;      // 0..7
    const int tig  = lane & 3;       // 0..3
    const int WM   = wid & 1;        // rows WM*32 .. +31 (within 64-row chunk)
    const int WN   = wid >> 1;       // cols WN*32 .. +31
    const int m0   = WM * 32;
    const int n0   = WN * 32;
    const int bi   = blockIdx.x;     // b*256 + i
    const int b    = bi >> 8;

    // ---- stage W1e (k-major, stride 132) ----
    {
        int k  = tid >> 3;               // 0..31
        int ng = (tid & 7) * 16;
        const float4* src = (const float4*)(W1e + k * 128 + ng);
#pragma unroll
        for (int c4 = 0; c4 < 4; c4++) {
            float4 v = src[c4];
            uint32_t* d = s32 + OFF_W1E + k * 132 + ng + c4 * 4;
            d[0] = f32_to_tf32(v.x); d[1] = f32_to_tf32(v.y);
            d[2] = f32_to_tf32(v.z); d[3] = f32_to_tf32(v.w);
        }
    }
    // ---- stage W2 (k-major, stride 132) ----
    {
        int k  = tid >> 1;               // 0..127
        int nb = (tid & 1) * 64;
        const float4* src = (const float4*)(W2 + k * 128 + nb);
#pragma unroll
        for (int c4 = 0; c4 < 16; c4++) {
            float4 v = src[c4];
            uint32_t* d = s32 + OFF_W2 + k * 132 + nb + c4 * 4;
            d[0] = f32_to_tf32(v.x); d[1] = f32_to_tf32(v.y);
            d[2] = f32_to_tf32(v.z); d[3] = f32_to_tf32(v.w);
        }
    }
    if (tid < 128) {
        smem[OFF_A  + tid] = A[(size_t)bi * 128 + tid];
        smem[OFF_B2 + tid] = b2[tid];
    }
    ((int*)(smem + OFF_ADJ))[tid] = adj[(size_t)bi * 256 + tid];

    // staging lambda-ish: chunk c -> buffer bsel
    const int srow = tid >> 2;           // 0..63
    const int eseg = (tid & 3) * 8;      // E: 8 words
    const int bseg = (tid & 3) * 32;     // BN: 32 words

#define STAGE_CHUNK(c, bsel)                                                     \
    {                                                                            \
        const int jj0 = (c) << 6;                                                \
        /* E rows (tf32) */                                                      \
        const float4* es = (const float4*)(e + ((size_t)bi * 256 + jj0 + srow) * 32 + eseg); \
        float4 v0 = es[0], v1 = es[1];                                           \
        uint32_t* ed = s32 + OFF_E + (bsel) * (64*36) + srow * 36 + eseg;        \
        ed[0] = f32_to_tf32(v0.x); ed[1] = f32_to_tf32(v0.y);                    \
        ed[2] = f32_to_tf32(v0.z); ed[3] = f32_to_tf32(v0.w);                    \
        ed[4] = f32_to_tf32(v1.x); ed[5] = f32_to_tf32(v1.y);                    \
        ed[6] = f32_to_tf32(v1.z); ed[7] = f32_to_tf32(v1.w);                    \
        /* Bnode rows (f32) */                                                   \
        const float4* bs = (const float4*)(Bnode + ((size_t)(b * 256 + jj0 + srow)) * 128 + bseg); \
        float4* bd = (float4*)(smem + OFF_BN + (bsel) * (64*132) + srow * 132 + bseg); \
        _Pragma("unroll")                                                        \
        for (int q8 = 0; q8 < 8; q8++) bd[q8] = bs[q8];                          \
    }

    STAGE_CHUNK(0, 0);
    __syncthreads();

    float pmax = 0.0f;

    for (int c = 0; c < 4; c++) {
        const int bsel = c & 1;
        const int j0   = c << 6;
        const uint32_t* sE  = (const uint32_t*)(s32 + OFF_E  + bsel * (64*36));
        const float*    sBN = smem + OFF_BN + bsel * (64*132);

        // prefetch next chunk into the other buffer (off critical path)
        if (c < 3) STAGE_CHUNK(c + 1, bsel ^ 1);

        float acc[2][4][4];
#pragma unroll
        for (int mt = 0; mt < 2; mt++)
#pragma unroll
            for (int nt = 0; nt < 4; nt++)
#pragma unroll
                for (int q = 0; q < 4; q++) acc[mt][nt][q] = 0.f;

        // ---- GEMM1: D1 = E @ W1e  (M=64, N=128 split, K=32) ----
#pragma unroll
        for (int ks = 0; ks < 4; ks++) {
            const int k0 = ks * 8;
            uint32_t af[2][4];
#pragma unroll
            for (int mt = 0; mt < 2; mt++) {
                const uint32_t* p = sE + (m0 + mt*16 + gid) * 36 + k0 + tig;
                af[mt][0] = p[0];
                af[mt][1] = p[8 * 36];
                af[mt][2] = p[4];
                af[mt][3] = p[8 * 36 + 4];
            }
#pragma unroll
            for (int nt = 0; nt < 4; nt++) {
                const uint32_t* q = s32 + OFF_W1E + (k0 + tig) * 132 + n0 + nt*8 + gid;
                uint32_t bf[2] = { q[0], q[4 * 132] };
                mma_16x8x8(acc[0][nt], af[0], bf);
                mma_16x8x8(acc[1][nt], af[1], bf);
            }
        }

        // ---- epilogue 1: H1 = relu(D1 + A_i[n] + Bnode[j,n]) -> tf32 smem ----
        {
            const float* sA_ = smem + OFF_A;
#pragma unroll
            for (int mt = 0; mt < 2; mt++) {
                const int r_lo = m0 + mt*16 + gid;
                const int r_hi = r_lo + 8;
                const float* blo = sBN + r_lo * 132;
                const float* bhi = sBN + r_hi * 132;
#pragma unroll
                for (int nt = 0; nt < 4; nt++) {
                    const int ncol = n0 + nt*8 + 2*tig;
                    float bl0 = blo[ncol], bl1 = blo[ncol+1];
                    float bh0 = bhi[ncol], bh1 = bhi[ncol+1];
                    float a0v = sA_[ncol], a1v = sA_[ncol + 1];
                    float h00 = fmaxf(acc[mt][nt][0] + a0v + bl0, 0.f);
                    float h01 = fmaxf(acc[mt][nt][1] + a1v + bl1, 0.f);
                    float h10 = fmaxf(acc[mt][nt][2] + a0v + bh0, 0.f);
                    float h11 = fmaxf(acc[mt][nt][3] + a1v + bh1, 0.f);
                    uint32_t* d0 = s32 + OFF_H1 + r_lo * 132 + ncol;
                    uint32_t* d1 = s32 + OFF_H1 + r_hi * 132 + ncol;
                    d0[0] = f32_to_tf32(h00); d0[1] = f32_to_tf32(h01);
                    d1[0] = f32_to_tf32(h10); d1[1] = f32_to_tf32(h11);
                }
            }
        }
        __syncthreads();

#pragma unroll
        for (int mt = 0; mt < 2; mt++)
#pragma unroll
            for (int nt = 0; nt < 4; nt++)
#pragma unroll
                for (int q = 0; q < 4; q++) acc[mt][nt][q] = 0.f;

        // ---- GEMM2: D2 = H1 @ W2  (K=128) ----
#pragma unroll 4
        for (int ks = 0; ks < 16; ks++) {
            const int k0 = ks * 8;
            uint32_t af[2][4];
#pragma unroll
            for (int mt = 0; mt < 2; mt++) {
                const uint32_t* p = s32 + OFF_H1 + (m0 + mt*16 + gid) * 132 + k0 + tig;
                af[mt][0] = p[0];
                af[mt][1] = p[8 * 132];
                af[mt][2] = p[4];
                af[mt][3] = p[8 * 132 + 4];
            }
#pragma unroll
            for (int nt = 0; nt < 4; nt++) {
                const uint32_t* q = s32 + OFF_W2 + (k0 + tig) * 132 + n0 + nt*8 + gid;
                uint32_t bf[2] = { q[0], q[4 * 132] };
                mma_16x8x8(acc[0][nt], af[0], bf);
                mma_16x8x8(acc[1][nt], af[1], bf);
            }
        }

        // ---- epilogue 2: bias+relu+mask, column max over rows ----
        {
            const int* sAdj = (const int*)(smem + OFF_ADJ);
            const float* sb2_ = smem + OFF_B2;
            float* red = smem + OFF_RED;
            const bool kLo0 = sAdj[j0 + m0      + gid] > 0;
            const bool kHi0 = sAdj[j0 + m0 +  8 + gid] > 0;
            const bool kLo1 = sAdj[j0 + m0 + 16 + gid] > 0;
            const bool kHi1 = sAdj[j0 + m0 + 24 + gid] > 0;
#pragma unroll
            for (int nt = 0; nt < 4; nt++) {
                const int ncol = n0 + nt*8 + 2*tig;
                const float bb0 = sb2_[ncol], bb1 = sb2_[ncol + 1];
                float vA = 0.f, vB = 0.f;
                if (kLo0) { vA = fmaxf(vA, acc[0][nt][0] + bb0);
                            vB = fmaxf(vB, acc[0][nt][1] + bb1); }
                if (kHi0) { vA = fmaxf(vA, acc[0][nt][2] + bb0);
                            vB = fmaxf(vB, acc[0][nt][3] + bb1); }
                if (kLo1) { vA = fmaxf(vA, acc[1][nt][0] + bb0);
                            vB = fmaxf(vB, acc[1][nt][1] + bb1); }
                if (kHi1) { vA = fmaxf(vA, acc[1][nt][2] + bb0);
                            vB = fmaxf(vB, acc[1][nt][3] + bb1); }
                // vA/vB already >= 0 (init 0 == relu floor)
#pragma unroll
                for (int msk = 4; msk <= 16; msk <<= 1) {
                    vA = fmaxf(vA, __shfl_xor_sync(0xffffffffu, vA, msk));
                    vB = fmaxf(vB, __shfl_xor_sync(0xffffffffu, vB, msk));
                }
                if (gid == 0) {
                    red[WM * 132 + ncol]     = vA;
                    red[WM * 132 + ncol + 1] = vB;
                }
            }
        }
        __syncthreads();
        if (tid < 128) {
            float v = fmaxf(smem[OFF_RED + tid], smem[OFF_RED + 132 + tid]);
            pmax = fmaxf(pmax, v);
        }
        __syncthreads();
    }

    if (tid < 128) xout[(size_t)bi * 128 + tid] = pmax;
#undef STAGE_CHUNK
}

// ---------------------------------------------------------------------------
// pair prep: 256 CTAs x 4 rows, 256 threads.
__global__ void pair_prep3(const float* __restrict__ x,     // (B*V,128)
                           const float* __restrict__ W3,    // (256,256)
                           float* __restrict__ P,
                           float* __restrict__ Q)
{
    __shared__ float sx[4 * 128];
    const int ni0 = blockIdx.x * 4;
    const int h   = threadIdx.x;     // 256
    for (int idx = h; idx < 4 * 128; idx += 256)
        sx[idx] = x[(size_t)ni0 * 128 + idx];
    __syncthreads();
    float accP[4] = {0.f, 0.f, 0.f, 0.f};
    float accQ[4] = {0.f, 0.f, 0.f, 0.f};
#pragma unroll 4
    for (int c = 0; c < 128; c++) {
        float wp = W3[c * 256 + h];
        float wq = W3[(128 + c) * 256 + h];
#pragma unroll
        for (int r = 0; r < 4; r++) {
            float xa = sx[r * 128 + c];
            accP[r] += xa * wp;
            accQ[r] += xa * wq;
        }
    }
#pragma unroll
    for (int r = 0; r < 4; r++) {
        P[(size_t)(ni0 + r) * 256 + h] = accP[r];
        Q[(size_t)(ni0 + r) * 256 + h] = accQ[r];
    }
}

// ---------------------------------------------------------------------------
// pair final: 256 CTAs; each handles (b, 4 i-rows) x all 256 j.
__global__ void pair_final3(const float* __restrict__ P,
                            const float* __restrict__ Q,
                            const float* __restrict__ b3,
                            const float* __restrict__ oW,
                            const float* __restrict__ ob,
                            float* __restrict__ out)        // (B,V,V)
{
    __shared__ float sQ[4 * 256];
    __shared__ float sW[256];
    const int blk = blockIdx.x;
    const int b   = blk >> 6;
    const int i0  = (blk & 63) * 4;
    const int tid = threadIdx.x;     // 256
    const int w   = tid >> 5, lane = tid & 31;
    sW[tid] = oW[tid];
    {
        float bb = b3[tid];
#pragma unroll
        for (int r = 0; r < 4; r++)
            sQ[r * 256 + tid] = Q[(size_t)(b * 256 + i0 + r) * 256 + tid] + bb;
    }
    __syncthreads();
    const float outb = ob[0];

    for (int j = w; j < 256; j += 8) {
        const float* pr = P + (size_t)(b * 256 + j) * 256;
        float s0 = 0.f, s1 = 0.f, s2 = 0.f, s3 = 0.f;
#pragma unroll
        for (int q = 0; q < 8; q++) {
            int hh = q * 32 + lane;
            float pv = pr[hh];
            float wv = sW[hh];
            s0 += fmaxf(pv + sQ[          hh], 0.f) * wv;
            s1 += fmaxf(pv + sQ[256     + hh], 0.f) * wv;
            s2 += fmaxf(pv + sQ[2 * 256 + hh], 0.f) * wv;
            s3 += fmaxf(pv + sQ[3 * 256 + hh], 0.f) * wv;
        }
#pragma unroll
        for (int off = 16; off > 0; off >>= 1) {
            s0 += __shfl_xor_sync(0xffffffffu, s0, off);
            s1 += __shfl_xor_sync(0xffffffffu, s1, off);
            s2 += __shfl_xor_sync(0xffffffffu, s2, off);
            s3 += __shfl_xor_sync(0xffffffffu, s3, off);
        }
        if (lane == 0) {
            out[(size_t)(b * 256 + i0 + 0) * 256 + j] = 1.0f / (1.0f + expf(-(s0 + outb)));
            out[(size_t)(b * 256 + i0 + 1) * 256 + j] = 1.0f / (1.0f + expf(-(s1 + outb)));
            out[(size_t)(b * 256 + i0 + 2) * 256 + j] = 1.0f / (1.0f + expf(-(s2 + outb)));
            out[(size_t)(b * 256 + i0 + 3) * 256 + j] = 1.0f / (1.0f + expf(-(s3 + outb)));
        }
    }
}

// ---------------------------------------------------------------------------
extern "C" void kernel_launch(void* const* d_in, const int* in_sizes, int n_in,
                              void* d_out, int out_size)
{
    const int*   adj   = (const int*)  d_in[0];
    const float* x0    = (const float*)d_in[1];
    const float* e     = (const float*)d_in[2];
    const float* ec1W1 = (const float*)d_in[3];
    const float* ec1b1 = (const float*)d_in[4];
    const float* ec1W2 = (const float*)d_in[5];
    const float* ec1b2 = (const float*)d_in[6];
    const float* ec2W1 = (const float*)d_in[7];
    const float* ec2b1 = (const float*)d_in[8];
    const float* ec2W2 = (const float*)d_in[9];
    const float* ec2b2 = (const float*)d_in[10];
    const float* h3W   = (const float*)d_in[11];
    const float* h3b   = (const float*)d_in[12];
    const float* oW    = (const float*)d_in[13];
    const float* ob    = (const float*)d_in[14];
    float* out = (float*)d_out;

    float *gA, *gB, *gx1, *gx2, *gP, *gQ;
    cudaGetSymbolAddress((void**)&gA,  g_A);
    cudaGetSymbolAddress((void**)&gB,  g_Bv);
    cudaGetSymbolAddress((void**)&gx1, g_x1);
    cudaGetSymbolAddress((void**)&gx2, g_x2);
    cudaGetSymbolAddress((void**)&gP,  g_P);
    cudaGetSymbolAddress((void**)&gQ,  g_Q);

    const int nBI = BN * VN;  // 1024
    cudaFuncSetAttribute(fused_ec_pipe,
                         cudaFuncAttributeMaxDynamicSharedMemorySize, SMEM_BYTES);

    // EdgeConvE #1
    prep_node3<C1N><<<256, 128>>>(x0, ec1W1, ec1b1, gA, gB);
    fused_ec_pipe<<<nBI, 256, SMEM_BYTES>>>(adj, e, gA, gB,
                                            ec1W1 + 2 * C1N * H0N, ec1W2, ec1b2, gx1);
    // EdgeConvE #2
    prep_node3<H0N><<<256, 128>>>(gx1, ec2W1, ec2b1, gA, gB);
    fused_ec_pipe<<<nBI, 256, SMEM_BYTES>>>(adj, e, gA, gB,
                                            ec2W1 + 2 * H0N * H0N, ec2W2, ec2b2, gx2);
    // pair scoring
    pair_prep3 <<<256, 256>>>(gx2, h3W, gP, gQ);
    pair_final3<<<256, 256>>>(gP, gQ, h3b, oW, ob, out);
}

// round 12
// speedup vs baseline: 2.3412x; 2.3412x over previous
#include <cuda_runtime.h>
#include <math.h>
#include <stdint.h>

#define BN   4
#define VN   256
#define C1N  64
#define C2N  32
#define H0N  128
#define H2N  256

// ---------------- scratch ----------------
__device__ float g_A [BN*VN*H0N];
__device__ float g_Bv[BN*VN*H0N];
__device__ float g_x1[BN*VN*H0N];
__device__ float g_x2[BN*VN*H0N];
__device__ float g_P [BN*VN*H2N];
__device__ float g_Q [BN*VN*H2N];

// pack two f32 -> bf16x2 (lo = first arg, hi = second)
__device__ __forceinline__ uint32_t pack_bf2(float lo, float hi) {
    uint32_t r;
    asm("cvt.rn.bf16x2.f32 %0, %1, %2;" : "=r"(r) : "f"(hi), "f"(lo));
    return r;
}
__device__ __forceinline__ void mma_bf16(float* c, const uint32_t* a, const uint32_t* b) {
    asm volatile("mma.sync.aligned.m16n8k16.row.col.f32.bf16.bf16.f32 "
        "{%0,%1,%2,%3}, {%4,%5,%6,%7}, {%8,%9}, {%0,%1,%2,%3};"
        : "+f"(c[0]), "+f"(c[1]), "+f"(c[2]), "+f"(c[3])
        : "r"(a[0]), "r"(a[1]), "r"(a[2]), "r"(a[3]), "r"(b[0]), "r"(b[1]));
}

// SMEM layout in 32-bit words. All matrices hold bf16x2 (2 k-values per word).
// W1E^T: [128 n][16 kw] stride 20 ; W2^T: [128 n][64 kw] stride 68
// E:     [128 j][16 kw] stride 20 ; H1:   [128 j][64 kw] stride 68
#define OFF_W1E 0
#define OFF_W2T (OFF_W1E + 128*20)     //  2560
#define OFF_E   (OFF_W2T + 128*68)     // 11264
#define OFF_H1  (OFF_E   + 128*20)     // 13824
#define OFF_A   (OFF_H1  + 128*68)     // 22528  (f32)
#define OFF_B2  (OFF_A + 128)
#define OFF_ADJ (OFF_B2 + 128)
#define OFF_RED (OFF_ADJ + 256)
#define SMEM_WORDS (OFF_RED + 4*132)   // 23568
#define SMEM_BYTES (SMEM_WORDS * 4)    // 94272 B  -> 2 CTAs/SM

// ---------------------------------------------------------------------------
// prep_node: 256 CTAs x 4 nodes, 128 threads.
template<int C>
__global__ void prep_node3(const float* __restrict__ x,
                           const float* __restrict__ W1,
                           const float* __restrict__ b1,
                           float* __restrict__ A,
                           float* __restrict__ Bout)
{
    __shared__ float sx[4 * C];
    const int ni0 = blockIdx.x * 4;
    const int h   = threadIdx.x;     // 128
    for (int idx = h; idx < 4 * C; idx += 128)
        sx[idx] = x[(size_t)ni0 * C + idx];
    __syncthreads();
    float accA[4] = {0.f, 0.f, 0.f, 0.f};
    float accB[4] = {0.f, 0.f, 0.f, 0.f};
#pragma unroll 4
    for (int c = 0; c < C; c++) {
        float wa = W1[c * 128 + h];
        float wb = W1[(C + c) * 128 + h];
        float d  = wa - wb;
#pragma unroll
        for (int r = 0; r < 4; r++) {
            float xa = sx[r * C + c];
            accA[r] += xa * d;
            accB[r] += xa * wb;
        }
    }
    const float bb = b1[h];
#pragma unroll
    for (int r = 0; r < 4; r++) {
        A   [(size_t)(ni0 + r) * 128 + h] = accA[r] + bb;
        Bout[(size_t)(ni0 + r) * 128 + h] = accB[r];
    }
}

// ---------------------------------------------------------------------------
// Fused edgeconv on bf16 tensor cores. One CTA per (b,i), 256 threads,
// 8 warps = 4 M-groups (32 rows) x 2 N-groups (64 cols). 2 chunks of 128 rows.
// 94KB smem -> 2 CTAs/SM.
__global__ __launch_bounds__(256, 2)
void fused_ec_bf16(const int*   __restrict__ adj,
                   const float* __restrict__ e,       // (B,V,V,32)
                   const float* __restrict__ A,
                   const float* __restrict__ Bnode,
                   const float* __restrict__ W1e,     // (32,128)
                   const float* __restrict__ W2,      // (128,128)
                   const float* __restrict__ b2,
                   float* __restrict__ xout)
{
    extern __shared__ float smem[];
    uint32_t* s32 = (uint32_t*)smem;
    const int tid  = threadIdx.x;
    const int lane = tid & 31;
    const int wid  = tid >> 5;
    const int gid  = lane >> 2;      // 0..7
    const int tig  = lane & 3;       // 0..3
    const int WM   = wid & 3;        // rows WM*32 .. +31
    const int WN   = wid >> 2;       // cols WN*64 .. +63
    const int m0   = WM * 32;
    const int n0   = WN * 64;
    const int bi   = blockIdx.x;     // b*256 + i
    const int b    = bi >> 8;

    // ---- stage W1e^T (n-major, k-paired, stride 20) ----
    {
        int n    = tid & 127;
        int half = tid >> 7;             // kw 0..7 or 8..15
#pragma unroll
        for (int kk = 0; kk < 8; kk++) {
            int kw = half * 8 + kk;
            float lo = W1e[(2*kw)     * 128 + n];
            float hi = W1e[(2*kw + 1) * 128 + n];
            s32[OFF_W1E + n * 20 + kw] = pack_bf2(lo, hi);
        }
    }
    // ---- stage W2^T (n-major, k-paired, stride 68) ----
    {
        int n    = tid & 127;
        int half = tid >> 7;             // kw 0..31 or 32..63
#pragma unroll 8
        for (int kk = 0; kk < 32; kk++) {
            int kw = half * 32 + kk;
            float lo = W2[(2*kw)     * 128 + n];
            float hi = W2[(2*kw + 1) * 128 + n];
            s32[OFF_W2T + n * 68 + kw] = pack_bf2(lo, hi);
        }
    }
    if (tid < 128) {
        smem[OFF_A  + tid] = A[(size_t)bi * 128 + tid];
        smem[OFF_B2 + tid] = b2[tid];
    }
    ((int*)(smem + OFF_ADJ))[tid] = adj[(size_t)bi * 256 + tid];

    float pmax = 0.0f;

    for (int chunk = 0; chunk < 2; chunk++) {
        const int j0 = chunk << 7;
        __syncthreads();   // red reuse from prior chunk + staging buffers free

        // ---- stage E chunk: 128 rows x 16 kw (stride 20) ----
        {
            int row  = tid >> 1;
            int half = tid & 1;
            const float4* src = (const float4*)(e + ((size_t)bi * 256 + j0 + row) * 32 + half * 16);
            float4 v0 = src[0], v1 = src[1], v2 = src[2], v3 = src[3];
            uint32_t* d = s32 + OFF_E + row * 20 + half * 8;
            d[0] = pack_bf2(v0.x, v0.y); d[1] = pack_bf2(v0.z, v0.w);
            d[2] = pack_bf2(v1.x, v1.y); d[3] = pack_bf2(v1.z, v1.w);
            d[4] = pack_bf2(v2.x, v2.y); d[5] = pack_bf2(v2.z, v2.w);
            d[6] = pack_bf2(v3.x, v3.y); d[7] = pack_bf2(v3.z, v3.w);
        }
        __syncthreads();

        float acc[2][8][4];
#pragma unroll
        for (int mt = 0; mt < 2; mt++)
#pragma unroll
            for (int nt = 0; nt < 8; nt++)
#pragma unroll
                for (int q = 0; q < 4; q++) acc[mt][nt][q] = 0.f;

        // ---- GEMM1: D1 = E @ W1e  (K=32 -> 2 bf16 k-steps) ----
#pragma unroll
        for (int ks = 0; ks < 2; ks++) {
            const int k0 = ks * 8;       // word offset
            uint32_t af[2][4];
#pragma unroll
            for (int mt = 0; mt < 2; mt++) {
                const uint32_t* p = s32 + OFF_E + (m0 + mt*16 + gid) * 20 + k0 + tig;
                af[mt][0] = p[0];
                af[mt][1] = p[8 * 20];
                af[mt][2] = p[4];
                af[mt][3] = p[8 * 20 + 4];
            }
#pragma unroll
            for (int nt = 0; nt < 8; nt++) {
                const uint32_t* q = s32 + OFF_W1E + (n0 + nt*8 + gid) * 20 + k0 + tig;
                uint32_t bf[2] = { q[0], q[4] };
                mma_bf16(acc[0][nt], af[0], bf);
                mma_bf16(acc[1][nt], af[1], bf);
            }
        }

        // ---- epilogue 1: H1 = relu(D1 + A_i[n] + Bnode[j,n]) -> bf16x2 ----
        {
            const float* sA_ = smem + OFF_A;
#pragma unroll
            for (int mt = 0; mt < 2; mt++) {
                const int r_lo = m0 + mt*16 + gid;
                const int r_hi = r_lo + 8;
                const float2* blo = (const float2*)(Bnode + ((size_t)(b*256 + j0 + r_lo)) * 128);
                const float2* bhi = (const float2*)(Bnode + ((size_t)(b*256 + j0 + r_hi)) * 128);
#pragma unroll
                for (int nt = 0; nt < 8; nt++) {
                    const int ncol = n0 + nt*8 + 2*tig;      // even
                    float2 bl = blo[ncol >> 1];
                    float2 bh = bhi[ncol >> 1];
                    float a0v = sA_[ncol], a1v = sA_[ncol + 1];
                    float h00 = fmaxf(acc[mt][nt][0] + a0v + bl.x, 0.f);
                    float h01 = fmaxf(acc[mt][nt][1] + a1v + bl.y, 0.f);
                    float h10 = fmaxf(acc[mt][nt][2] + a0v + bh.x, 0.f);
                    float h11 = fmaxf(acc[mt][nt][3] + a1v + bh.y, 0.f);
                    s32[OFF_H1 + r_lo * 68 + (ncol >> 1)] = pack_bf2(h00, h01);
                    s32[OFF_H1 + r_hi * 68 + (ncol >> 1)] = pack_bf2(h10, h11);
                }
            }
        }
        __syncthreads();

#pragma unroll
        for (int mt = 0; mt < 2; mt++)
#pragma unroll
            for (int nt = 0; nt < 8; nt++)
#pragma unroll
                for (int q = 0; q < 4; q++) acc[mt][nt][q] = 0.f;

        // ---- GEMM2: D2 = H1 @ W2  (K=128 -> 8 bf16 k-steps) ----
#pragma unroll 2
        for (int ks = 0; ks < 8; ks++) {
            const int k0 = ks * 8;
            uint32_t af[2][4];
#pragma unroll
            for (int mt = 0; mt < 2; mt++) {
                const uint32_t* p = s32 + OFF_H1 + (m0 + mt*16 + gid) * 68 + k0 + tig;
                af[mt][0] = p[0];
                af[mt][1] = p[8 * 68];
                af[mt][2] = p[4];
                af[mt][3] = p[8 * 68 + 4];
            }
#pragma unroll
            for (int nt = 0; nt < 8; nt++) {
                const uint32_t* q = s32 + OFF_W2T + (n0 + nt*8 + gid) * 68 + k0 + tig;
                uint32_t bf[2] = { q[0], q[4] };
                mma_bf16(acc[0][nt], af[0], bf);
                mma_bf16(acc[1][nt], af[1], bf);
            }
        }

        // ---- epilogue 2: bias+relu+mask, warp row-max -> red[WM][col] ----
        {
            const int* sAdj = (const int*)(smem + OFF_ADJ);
            const float* sb2_ = smem + OFF_B2;
            float* red = smem + OFF_RED;
            const bool kLo = sAdj[j0 + m0 + gid]      > 0;
            const bool kHi = sAdj[j0 + m0 + 8 + gid]  > 0;
            const bool kLo1 = sAdj[j0 + m0 + 16 + gid] > 0;
            const bool kHi1 = sAdj[j0 + m0 + 24 + gid] > 0;
#pragma unroll
            for (int nt = 0; nt < 8; nt++) {
                const int ncol = n0 + nt*8 + 2*tig;
                const float bb0 = sb2_[ncol], bb1 = sb2_[ncol + 1];
                float vA = 0.f, vB = 0.f;
                if (kLo)  { vA = fmaxf(vA, acc[0][nt][0] + bb0);
                            vB = fmaxf(vB, acc[0][nt][1] + bb1); }
                if (kHi)  { vA = fmaxf(vA, acc[0][nt][2] + bb0);
                            vB = fmaxf(vB, acc[0][nt][3] + bb1); }
                if (kLo1) { vA = fmaxf(vA, acc[1][nt][0] + bb0);
                            vB = fmaxf(vB, acc[1][nt][1] + bb1); }
                if (kHi1) { vA = fmaxf(vA, acc[1][nt][2] + bb0);
                            vB = fmaxf(vB, acc[1][nt][3] + bb1); }
                // vA/vB >= 0 already encodes relu + isolated-node zero
#pragma unroll
                for (int msk = 4; msk <= 16; msk <<= 1) {
                    vA = fmaxf(vA, __shfl_xor_sync(0xffffffffu, vA, msk));
                    vB = fmaxf(vB, __shfl_xor_sync(0xffffffffu, vB, msk));
                }
                if (gid == 0) {
                    red[WM * 132 + ncol]     = vA;
                    red[WM * 132 + ncol + 1] = vB;
                }
            }
        }
        __syncthreads();
        if (tid < 128) {
            float v = fmaxf(fmaxf(smem[OFF_RED + tid],          smem[OFF_RED + 132 + tid]),
                            fmaxf(smem[OFF_RED + 2*132 + tid],  smem[OFF_RED + 3*132 + tid]));
            pmax = fmaxf(pmax, v);
        }
    }

    if (tid < 128) xout[(size_t)bi * 128 + tid] = pmax;
}

// ---------------------------------------------------------------------------
// pair prep: 256 CTAs x 4 rows, 256 threads.
__global__ void pair_prep3(const float* __restrict__ x,     // (B*V,128)
                           const float* __restrict__ W3,    // (256,256)
                           float* __restrict__ P,
                           float* __restrict__ Q)
{
    __shared__ float sx[4 * 128];
    const int ni0 = blockIdx.x * 4;
    const int h   = threadIdx.x;     // 256
    for (int idx = h; idx < 4 * 128; idx += 256)
        sx[idx] = x[(size_t)ni0 * 128 + idx];
    __syncthreads();
    float accP[4] = {0.f, 0.f, 0.f, 0.f};
    float accQ[4] = {0.f, 0.f, 0.f, 0.f};
#pragma unroll 4
    for (int c = 0; c < 128; c++) {
        float wp = W3[c * 256 + h];
        float wq = W3[(128 + c) * 256 + h];
#pragma unroll
        for (int r = 0; r < 4; r++) {
            float xa = sx[r * 128 + c];
            accP[r] += xa * wp;
            accQ[r] += xa * wq;
        }
    }
#pragma unroll
    for (int r = 0; r < 4; r++) {
        P[(size_t)(ni0 + r) * 256 + h] = accP[r];
        Q[(size_t)(ni0 + r) * 256 + h] = accQ[r];
    }
}

// ---------------------------------------------------------------------------
// pair final: 256 CTAs; each handles (b, 4 i-rows) x all 256 j.
__global__ void pair_final3(const float* __restrict__ P,
                            const float* __restrict__ Q,
                            const float* __restrict__ b3,
                            const float* __restrict__ oW,
                            const float* __restrict__ ob,
                            float* __restrict__ out)        // (B,V,V)
{
    __shared__ float sQ[4 * 256];
    __shared__ float sW[256];
    const int blk = blockIdx.x;
    const int b   = blk >> 6;
    const int i0  = (blk & 63) * 4;
    const int tid = threadIdx.x;     // 256
    const int w   = tid >> 5, lane = tid & 31;
    sW[tid] = oW[tid];
    {
        float bb = b3[tid];
#pragma unroll
        for (int r = 0; r < 4; r++)
            sQ[r * 256 + tid] = Q[(size_t)(b * 256 + i0 + r) * 256 + tid] + bb;
    }
    __syncthreads();
    const float outb = ob[0];

    for (int j = w; j < 256; j += 8) {
        const float* pr = P + (size_t)(b * 256 + j) * 256;
        float s0 = 0.f, s1 = 0.f, s2 = 0.f, s3 = 0.f;
#pragma unroll
        for (int q = 0; q < 8; q++) {
            int hh = q * 32 + lane;
            float pv = pr[hh];
            float wv = sW[hh];
            s0 += fmaxf(pv + sQ[          hh], 0.f) * wv;
            s1 += fmaxf(pv + sQ[256     + hh], 0.f) * wv;
            s2 += fmaxf(pv + sQ[2 * 256 + hh], 0.f) * wv;
            s3 += fmaxf(pv + sQ[3 * 256 + hh], 0.f) * wv;
        }
#pragma unroll
        for (int off = 16; off > 0; off >>= 1) {
            s0 += __shfl_xor_sync(0xffffffffu, s0, off);
            s1 += __shfl_xor_sync(0xffffffffu, s1, off);
            s2 += __shfl_xor_sync(0xffffffffu, s2, off);
            s3 += __shfl_xor_sync(0xffffffffu, s3, off);
        }
        if (lane == 0) {
            out[(size_t)(b * 256 + i0 + 0) * 256 + j] = 1.0f / (1.0f + expf(-(s0 + outb)));
            out[(size_t)(b * 256 + i0 + 1) * 256 + j] = 1.0f / (1.0f + expf(-(s1 + outb)));
            out[(size_t)(b * 256 + i0 + 2) * 256 + j] = 1.0f / (1.0f + expf(-(s2 + outb)));
            out[(size_t)(b * 256 + i0 + 3) * 256 + j] = 1.0f / (1.0f + expf(-(s3 + outb)));
        }
    }
}

// ---------------------------------------------------------------------------
extern "C" void kernel_launch(void* const* d_in, const int* in_sizes, int n_in,
                              void* d_out, int out_size)
{
    const int*   adj   = (const int*)  d_in[0];
    const float* x0    = (const float*)d_in[1];
    const float* e     = (const float*)d_in[2];
    const float* ec1W1 = (const float*)d_in[3];
    const float* ec1b1 = (const float*)d_in[4];
    const float* ec1W2 = (const float*)d_in[5];
    const float* ec1b2 = (const float*)d_in[6];
    const float* ec2W1 = (const float*)d_in[7];
    const float* ec2b1 = (const float*)d_in[8];
    const float* ec2W2 = (const float*)d_in[9];
    const float* ec2b2 = (const float*)d_in[10];
    const float* h3W   = (const float*)d_in[11];
    const float* h3b   = (const float*)d_in[12];
    const float* oW    = (const float*)d_in[13];
    const float* ob    = (const float*)d_in[14];
    float* out = (float*)d_out;

    float *gA, *gB, *gx1, *gx2, *gP, *gQ;
    cudaGetSymbolAddress((void**)&gA,  g_A);
    cudaGetSymbolAddress((void**)&gB,  g_Bv);
    cudaGetSymbolAddress((void**)&gx1, g_x1);
    cudaGetSymbolAddress((void**)&gx2, g_x2);
    cudaGetSymbolAddress((void**)&gP,  g_P);
    cudaGetSymbolAddress((void**)&gQ,  g_Q);

    const int nBI = BN * VN;  // 1024
    cudaFuncSetAttribute(fused_ec_bf16,
                         cudaFuncAttributeMaxDynamicSharedMemorySize, SMEM_BYTES);

    // EdgeConvE #1
    prep_node3<C1N><<<256, 128>>>(x0, ec1W1, ec1b1, gA, gB);
    fused_ec_bf16<<<nBI, 256, SMEM_BYTES>>>(adj, e, gA, gB,
                                            ec1W1 + 2 * C1N * H0N, ec1W2, ec1b2, gx1);
    // EdgeConvE #2
    prep_node3<H0N><<<256, 128>>>(gx1, ec2W1, ec2b1, gA, gB);
    fused_ec_bf16<<<nBI, 256, SMEM_BYTES>>>(adj, e, gA, gB,
                                            ec2W1 + 2 * H0N * H0N, ec2W2, ec2b2, gx2);
    // pair scoring
    pair_prep3 <<<256, 256>>>(gx2, h3W, gP, gQ);
    pair_final3<<<256, 256>>>(gP, gQ, h3b, oW, ob, out);
}